// round 1
// baseline (speedup 1.0000x reference)
#include <cuda_runtime.h>
#include <math.h>

#define SB    1024      // sequence length S
#define NB    32        // batch B
#define NG    5         // gt windows per batch
#define TK    5         // top-k
#define EPSF  1e-7f
#define NLBLK 32        // label-loss blocks
#define NTHR  256

// Per-block partial results (written fresh every launch -> deterministic, graph-safe)
__device__ float g_spans[NB];
__device__ float g_labels[NLBLK];

__device__ __forceinline__ float sigf(float x) { return 1.0f / (1.0f + expf(-x)); }

// jax.lax.top_k ordering: larger value first; ties -> smaller flat index first
__device__ __forceinline__ bool better(float s1, int i1, float s2, int i2) {
    return (s1 > s2) || (s1 == s2 && i1 < i2);
}

// Insert candidate into sorted (desc) 5-list held in registers.
// All indices constant after unroll -> stays in registers.
__device__ __forceinline__ void tryins(float* s5, int* i5, float v, int id) {
    if (v > s5[TK - 1] || (v == s5[TK - 1] && id < i5[TK - 1])) {
        float ts = v; int ti = id;
#pragma unroll
        for (int k = 0; k < TK; k++) {
            if (better(ts, ti, s5[k], i5[k])) {
                float a = s5[k]; int b = i5[k];
                s5[k] = ts; i5[k] = ti;
                ts = a; ti = b;
            }
        }
    }
}

__device__ __forceinline__ float wbce(float x, float tg) {
    float p = fminf(fmaxf(1.0f / (1.0f + expf(-x)), EPSF), 1.0f - EPSF);
    float b = -(tg * logf(p) + (1.0f - tg) * logf(1.0f - p));
    float d = fabsf(p - tg);            // GAMMA = 2 -> weight = d*d
    return b * d * d;
}

__global__ void __launch_bounds__(NTHR)
crit_main(const float* __restrict__ fp, const float* __restrict__ sl,
          const float* __restrict__ ml, const float* __restrict__ el,
          const float* __restrict__ gt, const int* __restrict__ smsp) {
    __shared__ __align__(16) float sp[SB];
    __shared__ __align__(16) float ep[SB];
    __shared__ float cs[NTHR * TK];
    __shared__ int   ci[NTHR * TK];

    const int t   = threadIdx.x;
    const int blk = blockIdx.x;

    if (blk < NB) {
        // ---------------- spans loss: one block per batch ----------------
        const int b = blk;
        const float4* fp4 = ((const float4*)fp) + b * SB;
        for (int s = t; s < SB; s += NTHR) {
            float4 v = fp4[s];
            sp[s] = sigf(v.x);   // start prob
            ep[s] = sigf(v.z);   // end prob
        }
        __syncthreads();

        float s5[TK]; int i5[TK];
#pragma unroll
        for (int k = 0; k < TK; k++) { s5[k] = -1.0f; i5[k] = 0x7fffffff; }

        // Mirror-paired rows: every thread scans exactly ~2050 valid pairs
        const int rows[4] = { t, 1023 - t, 256 + t, 767 - t };
#pragma unroll
        for (int r = 0; r < 4; r++) {
            const int i = rows[r];
            const float spi = sp[i];
            const int base = i << 10;
            int j = i;
            for (; j < SB && (j & 3); j++) tryins(s5, i5, spi * ep[j], base + j);
            const float4* ep4 = (const float4*)ep;
            for (; j < SB; j += 4) {
                float4 e = ep4[j >> 2];
                float p0 = spi * e.x, p1 = spi * e.y, p2 = spi * e.z, p3 = spi * e.w;
                float m = fmaxf(fmaxf(p0, p1), fmaxf(p2, p3));
                if (m >= s5[TK - 1]) {       // >= keeps tie/index correctness
                    tryins(s5, i5, p0, base + j);
                    tryins(s5, i5, p1, base + j + 1);
                    tryins(s5, i5, p2, base + j + 2);
                    tryins(s5, i5, p3, base + j + 3);
                }
            }
        }

#pragma unroll
        for (int k = 0; k < TK; k++) { cs[t * TK + k] = s5[k]; ci[t * TK + k] = i5[k]; }
        __syncthreads();

        // Tree merge of sorted 5-lists: 256 -> 1
        for (int stride = NTHR / 2; stride >= 1; stride >>= 1) {
            if (t < stride) {
                const int A = t * TK, Bo = (t + stride) * TK;
                float os[TK]; int oi[TK];
                int pa = 0, pb = 0;
#pragma unroll
                for (int k = 0; k < TK; k++) {
                    float as_ = cs[A + pa];  int ai_ = ci[A + pa];
                    float bs_ = cs[Bo + pb]; int bi_ = ci[Bo + pb];
                    if (better(as_, ai_, bs_, bi_)) { os[k] = as_; oi[k] = ai_; pa++; }
                    else                            { os[k] = bs_; oi[k] = bi_; pb++; }
                }
#pragma unroll
                for (int k = 0; k < TK; k++) { cs[A + k] = os[k]; ci[A + k] = oi[k]; }
            }
            __syncthreads();
        }

        // GIoU on lanes 0..4 of warp 0, then warp reduce
        if (t < 32) {
            float val = 0.0f;
            if (t < TK) {
                float conf = cs[t]; int fid = ci[t];
                int i = fid >> 10, j = fid & (SB - 1);
                float smsf = (float)smsp[b];
                float pst = (float)i + smsf;
                float ped = (float)j + smsf;
                float best = -INFINITY;
#pragma unroll
                for (int g = 0; g < NG; g++) {
                    float gst = gt[(b * NG + g) * 2 + 0];
                    float ged = gt[(b * NG + g) * 2 + 1];
                    float inter = fmaxf(fminf(ped, ged) - fmaxf(pst, gst), 0.0f);
                    float uni   = (ped - pst) + (ged - gst) - inter;
                    float iou   = inter / fmaxf(uni, EPSF);
                    float enc   = fmaxf(fmaxf(ped, ged) - fminf(pst, gst), 0.0f);
                    float gi    = iou - (enc - uni) / fmaxf(enc, EPSF);
                    best = fmaxf(best, gi);
                }
                float d = conf - best;
                val = d * d;
            }
#pragma unroll
            for (int off = 16; off; off >>= 1)
                val += __shfl_down_sync(0xffffffffu, val, off);
            if (t == 0) g_spans[b] = val;
        }
    } else {
        // ---------------- label loss (weighted BCE x3) ----------------
        const int lb = blk - NB;
        const float4* fp4 = (const float4*)fp;
        float acc = 0.0f;
        for (int idx = lb * NTHR + t; idx < NB * SB; idx += NLBLK * NTHR) {
            float4 v = fp4[idx];
            acc += wbce(v.x, sl[idx]);
            acc += wbce(v.y, ml[idx]);
            acc += wbce(v.z, el[idx]);
        }
#pragma unroll
        for (int off = 16; off; off >>= 1)
            acc += __shfl_down_sync(0xffffffffu, acc, off);
        if ((t & 31) == 0) cs[t >> 5] = acc;
        __syncthreads();
        if (t == 0) {
            float s = 0.0f;
            for (int w = 0; w < NTHR / 32; w++) s += cs[w];
            g_labels[lb] = s;
        }
    }
}

__global__ void crit_final(float* out) {
    float s = 0.0f, l = 0.0f;
#pragma unroll
    for (int i = 0; i < NB; i++)    s += g_spans[i];
#pragma unroll
    for (int i = 0; i < NLBLK; i++) l += g_labels[i];
    // spans mean over B*K = 160; labels: (sum0+sum1+sum2)/(B*S) = /32768
    out[0] = s * (1.0f / 160.0f) + l * (1.0f / 32768.0f);
}

extern "C" void kernel_launch(void* const* d_in, const int* in_sizes, int n_in,
                              void* d_out, int out_size) {
    const float* fp  = (const float*)d_in[0];
    const float* sl  = (const float*)d_in[1];
    const float* ml  = (const float*)d_in[2];
    const float* el  = (const float*)d_in[3];
    const float* gt  = (const float*)d_in[4];
    const int*   sms = (const int*)d_in[5];

    crit_main<<<NB + NLBLK, NTHR>>>(fp, sl, ml, el, gt, sms);
    crit_final<<<1, 1>>>((float*)d_out);
}

// round 2
// speedup vs baseline: 1.7280x; 1.7280x over previous
#include <cuda_runtime.h>
#include <math.h>

#define SB     1024      // sequence length S
#define NB     32        // batch B
#define NG     5         // gt windows per batch
#define TK     5         // top-k
#define EPSF   1e-7f
#define NLBLK  32        // label-loss blocks
#define NTHR   256
#define CAP    1024      // candidate buffer capacity
#define NEGINF (-1e30f)

// Per-block partials + completion counter (returns to 0 every launch -> graph-safe)
__device__ float g_spans[NB];
__device__ float g_labels[NLBLK];
__device__ unsigned g_done = 0;

__device__ __forceinline__ float sigf(float x) { return 1.0f / (1.0f + expf(-x)); }

// jax.lax.top_k ordering: larger value first; ties -> smaller flat index first
__device__ __forceinline__ bool better(float s1, int i1, float s2, int i2) {
    return (s1 > s2) || (s1 == s2 && i1 < i2);
}

__device__ __forceinline__ void tryins(float* s5, int* i5, float v, int id) {
    if (v > s5[TK - 1] || (v == s5[TK - 1] && id < i5[TK - 1])) {
        float ts = v; int ti = id;
#pragma unroll
        for (int k = 0; k < TK; k++) {
            if (better(ts, ti, s5[k], i5[k])) {
                float a = s5[k]; int b = i5[k];
                s5[k] = ts; i5[k] = ti;
                ts = a; ti = b;
            }
        }
    }
}

__device__ __forceinline__ float wbce(float x, float tg) {
    float p = fminf(fmaxf(1.0f / (1.0f + expf(-x)), EPSF), 1.0f - EPSF);
    float b = -(tg * logf(p) + (1.0f - tg) * logf(1.0f - p));
    float d = fabsf(p - tg);            // GAMMA = 2 -> weight = d*d
    return b * d * d;
}

__global__ void __launch_bounds__(NTHR)
crit_all(const float* __restrict__ fp, const float* __restrict__ sl,
         const float* __restrict__ ml, const float* __restrict__ el,
         const float* __restrict__ gt, const int* __restrict__ smsp,
         float* __restrict__ out) {
    __shared__ __align__(16) float sp[SB];
    __shared__ __align__(16) float ep[SB];
    __shared__ float segm[NTHR];
    __shared__ float warpL[NTHR / 32];
    __shared__ __align__(16) float cands[CAP];
    __shared__ int   candi[CAP];
    __shared__ float cs[NTHR * TK];
    __shared__ int   ci[NTHR * TK];
    __shared__ int   cnt;

    const int t    = threadIdx.x;
    const int blk  = blockIdx.x;
    const int lane = t & 31;

    if (blk < NB) {
        // ================= spans loss: one block per batch =================
        const int b = blk;
        if (t == 0) cnt = 0;
        const float4* fp4 = ((const float4*)fp) + b * SB;
        for (int s = t; s < SB; s += NTHR) {
            float4 v = fp4[s];
            sp[s] = sigf(v.x);   // start prob
            ep[s] = sigf(v.z);   // end prob
        }
        __syncthreads();

        // ---- suffix max of ep: thread t owns elements [4t, 4t+4) ----
        const float e0 = ep[4 * t], e1 = ep[4 * t + 1], e2 = ep[4 * t + 2], e3 = ep[4 * t + 3];
        segm[t] = fmaxf(fmaxf(e0, e1), fmaxf(e2, e3));
        __syncthreads();
        for (int off = 1; off < NTHR; off <<= 1) {
            float a  = segm[t];
            float bb = (t + off < NTHR) ? segm[t + off] : NEGINF;
            __syncthreads();
            segm[t] = fmaxf(a, bb);
            __syncthreads();
        }
        const float snext = (t + 1 < NTHR) ? segm[t + 1] : NEGINF;
        const float sf3 = fmaxf(e3, snext);
        const float sf2 = fmaxf(e2, sf3);
        const float sf1 = fmaxf(e1, sf2);
        const float sf0 = fmaxf(e0, sf1);
        const float s0 = sp[4 * t], s1 = sp[4 * t + 1], s2 = sp[4 * t + 2], s3 = sp[4 * t + 3];
        const float u0 = s0 * sf0, u1 = s1 * sf1, u2 = s2 * sf2, u3 = s3 * sf3;

        // ---- exact warp 5th-largest of the warp's 128 u values ----
        {
            float a = u0, bv = u1, c = u2, d = u3;
            float wm = NEGINF;
            const unsigned FULL = 0xffffffffu;
#pragma unroll
            for (int r = 0; r < TK; r++) {
                float lm = fmaxf(fmaxf(a, bv), fmaxf(c, d));
                float m = lm;
#pragma unroll
                for (int o = 16; o; o >>= 1) m = fmaxf(m, __shfl_xor_sync(FULL, m, o));
                unsigned bal = __ballot_sync(FULL, lm == m);
                if (lane == (__ffs(bal) - 1)) {  // exactly one lane removes one instance
                    if (a == m) a = NEGINF;
                    else if (bv == m) bv = NEGINF;
                    else if (c == m) c = NEGINF;
                    else d = NEGINF;
                }
                wm = m;
            }
            if (lane == 0) warpL[t >> 5] = wm;
        }
        __syncthreads();
        float L = warpL[0];
#pragma unroll
        for (int w = 1; w < NTHR / 32; w++) L = fmaxf(L, warpL[w]);
        // L <= global 5th-largest pair score  =>  top-5 pairs all have score >= L

        // ---- collect candidate pairs with score >= L ----
        const float us[4] = { u0, u1, u2, u3 };
        const float ss[4] = { s0, s1, s2, s3 };
#pragma unroll
        for (int k = 0; k < 4; k++) {
            if (us[k] >= L) {                       // row prune (monotone upper bound)
                const int i = 4 * t + k;
                const float spi = ss[k];
                const int base = i << 10;
                int j = i;
                for (; j < SB && (j & 3); j++) {
                    float v = spi * ep[j];
                    if (v >= L) { int p = atomicAdd(&cnt, 1); if (p < CAP) { cands[p] = v; candi[p] = base + j; } }
                }
                const float4* e4 = (const float4*)ep;
                for (; j < SB; j += 4) {
                    float4 e = e4[j >> 2];
                    float p0 = spi * e.x, p1 = spi * e.y, p2 = spi * e.z, p3 = spi * e.w;
                    if (fmaxf(fmaxf(p0, p1), fmaxf(p2, p3)) >= L) {
                        if (p0 >= L) { int p = atomicAdd(&cnt, 1); if (p < CAP) { cands[p] = p0; candi[p] = base + j; } }
                        if (p1 >= L) { int p = atomicAdd(&cnt, 1); if (p < CAP) { cands[p] = p1; candi[p] = base + j + 1; } }
                        if (p2 >= L) { int p = atomicAdd(&cnt, 1); if (p < CAP) { cands[p] = p2; candi[p] = base + j + 2; } }
                        if (p3 >= L) { int p = atomicAdd(&cnt, 1); if (p < CAP) { cands[p] = p3; candi[p] = base + j + 3; } }
                    }
                }
            }
        }
        __syncthreads();
        const int C = cnt;

        // ---- per-thread top-5 over candidates (or full-scan fallback) ----
        float s5[TK]; int i5[TK];
#pragma unroll
        for (int k = 0; k < TK; k++) { s5[k] = -1.0f; i5[k] = 0x7fffffff; }
        if (C <= CAP) {
            for (int p = t; p < C; p += NTHR) tryins(s5, i5, cands[p], candi[p]);
        } else {
            // safety fallback: exact full scan (never triggers on benign data)
            const int rows[4] = { t, 1023 - t, 256 + t, 767 - t };
#pragma unroll
            for (int r = 0; r < 4; r++) {
                const int i = rows[r];
                const float spi = sp[i];
                const int base = i << 10;
                for (int j = i; j < SB; j++) tryins(s5, i5, spi * ep[j], base + j);
            }
        }
#pragma unroll
        for (int k = 0; k < TK; k++) { cs[t * TK + k] = s5[k]; ci[t * TK + k] = i5[k]; }
        __syncthreads();

        // ---- tree merge of sorted 5-lists: 256 -> 1 ----
        for (int stride = NTHR / 2; stride >= 1; stride >>= 1) {
            if (t < stride) {
                const int A = t * TK, Bo = (t + stride) * TK;
                float os[TK]; int oi[TK];
                int pa = 0, pb = 0;
#pragma unroll
                for (int k = 0; k < TK; k++) {
                    float as_ = cs[A + pa];  int ai_ = ci[A + pa];
                    float bs_ = cs[Bo + pb]; int bi_ = ci[Bo + pb];
                    if (better(as_, ai_, bs_, bi_)) { os[k] = as_; oi[k] = ai_; pa++; }
                    else                            { os[k] = bs_; oi[k] = bi_; pb++; }
                }
#pragma unroll
                for (int k = 0; k < TK; k++) { cs[A + k] = os[k]; ci[A + k] = oi[k]; }
            }
            __syncthreads();
        }

        // ---- GIoU on lanes 0..4, warp reduce ----
        if (t < 32) {
            float val = 0.0f;
            if (t < TK) {
                float conf = cs[t]; int fid = ci[t];
                int i = fid >> 10, j = fid & (SB - 1);
                float smsf = (float)smsp[b];
                float pst = (float)i + smsf;
                float ped = (float)j + smsf;
                float best = -INFINITY;
#pragma unroll
                for (int g = 0; g < NG; g++) {
                    float gst = gt[(b * NG + g) * 2 + 0];
                    float ged = gt[(b * NG + g) * 2 + 1];
                    float inter = fmaxf(fminf(ped, ged) - fmaxf(pst, gst), 0.0f);
                    float uni   = (ped - pst) + (ged - gst) - inter;
                    float iou   = inter / fmaxf(uni, EPSF);
                    float enc   = fmaxf(fmaxf(ped, ged) - fminf(pst, gst), 0.0f);
                    float gi    = iou - (enc - uni) / fmaxf(enc, EPSF);
                    best = fmaxf(best, gi);
                }
                float d = conf - best;
                val = d * d;
            }
#pragma unroll
            for (int off = 16; off; off >>= 1)
                val += __shfl_down_sync(0xffffffffu, val, off);
            if (t == 0) g_spans[b] = val;
        }
    } else {
        // ================= label loss (weighted BCE x3) =================
        const int lb = blk - NB;
        const float4* fp4 = (const float4*)fp;
        float acc = 0.0f;
        for (int idx = lb * NTHR + t; idx < NB * SB; idx += NLBLK * NTHR) {
            float4 v = fp4[idx];
            acc += wbce(v.x, sl[idx]);
            acc += wbce(v.y, ml[idx]);
            acc += wbce(v.z, el[idx]);
        }
#pragma unroll
        for (int off = 16; off; off >>= 1)
            acc += __shfl_down_sync(0xffffffffu, acc, off);
        if (lane == 0) cs[t >> 5] = acc;
        __syncthreads();
        if (t == 0) {
            float s = 0.0f;
            for (int w = 0; w < NTHR / 32; w++) s += cs[w];
            g_labels[lb] = s;
        }
    }

    // ================= last block finalizes =================
    if (t == 0) {
        __threadfence();
        unsigned v = atomicAdd(&g_done, 1u);
        if (v == (unsigned)(NB + NLBLK - 1)) {
            __threadfence();
            float s = 0.0f, l = 0.0f;
#pragma unroll
            for (int i = 0; i < NB; i++)    s += g_spans[i];
#pragma unroll
            for (int i = 0; i < NLBLK; i++) l += g_labels[i];
            out[0] = s * (1.0f / 160.0f) + l * (1.0f / 32768.0f);
            g_done = 0;   // reset for next graph replay
        }
    }
}

extern "C" void kernel_launch(void* const* d_in, const int* in_sizes, int n_in,
                              void* d_out, int out_size) {
    const float* fp  = (const float*)d_in[0];
    const float* sl  = (const float*)d_in[1];
    const float* ml  = (const float*)d_in[2];
    const float* el  = (const float*)d_in[3];
    const float* gt  = (const float*)d_in[4];
    const int*   sms = (const int*)d_in[5];

    crit_all<<<NB + NLBLK, NTHR>>>(fp, sl, ml, el, gt, sms, (float*)d_out);
}

// round 3
// speedup vs baseline: 11.2337x; 6.5011x over previous
#include <cuda_runtime.h>
#include <math.h>
#include <float.h>

#define SB     1024
#define NB     32
#define NG     5
#define TK     5
#define EPSF   1e-7f
#define NLBLK  32
#define NTHR   256
#define CAP    1024
#define NEGINF (-1e30f)
#define FULLM  0xffffffffu

__device__ float g_spans[NB];
__device__ float g_labels[NLBLK];
__device__ unsigned g_done = 0;

__device__ __forceinline__ float sigf(float x) { return 1.0f / (1.0f + __expf(-x)); }

// jax.lax.top_k ordering: larger value first; ties -> smaller flat index first
__device__ __forceinline__ bool better(float s1, int i1, float s2, int i2) {
    return (s1 > s2) || (s1 == s2 && i1 < i2);
}

__device__ __forceinline__ void tryins(float* s5, int* i5, float v, int id) {
    if (v > s5[TK - 1] || (v == s5[TK - 1] && id < i5[TK - 1])) {
        float ts = v; int ti = id;
#pragma unroll
        for (int k = 0; k < TK; k++) {
            if (better(ts, ti, s5[k], i5[k])) {
                float a = s5[k]; int b = i5[k];
                s5[k] = ts; i5[k] = ti;
                ts = a; ti = b;
            }
        }
    }
}

__device__ __forceinline__ float wbce(float x, float tg) {
    float p = fminf(fmaxf(sigf(x), EPSF), 1.0f - EPSF);
    float b = -(tg * __logf(p) + (1.0f - tg) * __logf(1.0f - p));
    float d = fabsf(p - tg);
    return b * d * d;
}

__global__ void __launch_bounds__(NTHR)
crit_all(const float* __restrict__ fp, const float* __restrict__ sl,
         const float* __restrict__ ml, const float* __restrict__ el,
         const float* __restrict__ gt, const int* __restrict__ smsp,
         float* __restrict__ out) {
    __shared__ __align__(16) float sp[SB];
    __shared__ __align__(16) float ep[SB];
    __shared__ __align__(16) float us[SB];
    __shared__ __align__(16) float cands[CAP];
    __shared__ int   candi[CAP];
    __shared__ int   rlist[SB];
    __shared__ float rs[SB];
    __shared__ float warpM[NTHR / 32];
    __shared__ float sh_L;
    __shared__ float fin_s[TK];
    __shared__ int   fin_i[TK];
    __shared__ int   cnt, rown;
    __shared__ float wsum[NTHR / 32];

    const int t    = threadIdx.x;
    const int blk  = blockIdx.x;
    const int lane = t & 31;
    const int w    = t >> 5;

    if (blk < NB) {
        // ================= spans loss: one block per batch =================
        const int b = blk;
        if (t == 0) { cnt = 0; rown = 0; }
        const float4* fp4 = ((const float4*)fp) + b * SB;
        // thread t owns elements [4t, 4t+4)
        float4 va = fp4[4 * t], vb = fp4[4 * t + 1], vc = fp4[4 * t + 2], vd = fp4[4 * t + 3];
        const float s0 = sigf(va.x), s1 = sigf(vb.x), s2 = sigf(vc.x), s3 = sigf(vd.x);
        const float e0 = sigf(va.z), e1 = sigf(vb.z), e2 = sigf(vc.z), e3 = sigf(vd.z);
        sp[4 * t] = s0; sp[4 * t + 1] = s1; sp[4 * t + 2] = s2; sp[4 * t + 3] = s3;
        ep[4 * t] = e0; ep[4 * t + 1] = e1; ep[4 * t + 2] = e2; ep[4 * t + 3] = e3;

        // ---- suffix max of ep via shfl ----
        float lm = fmaxf(fmaxf(e0, e1), fmaxf(e2, e3));
        float inc = lm;
#pragma unroll
        for (int o = 1; o < 32; o <<= 1) {
            float v = __shfl_down_sync(FULLM, inc, o);
            if (lane + o < 32) inc = fmaxf(inc, v);
        }
        float excl = __shfl_down_sync(FULLM, inc, 1);
        if (lane == 31) excl = NEGINF;
        if (lane == 0) warpM[w] = inc;     // warp max
        __syncthreads();
        float suffW = NEGINF;
#pragma unroll
        for (int ww = 0; ww < NTHR / 32; ww++)
            if (ww > w) suffW = fmaxf(suffW, warpM[ww]);
        const float tail = fmaxf(excl, suffW);   // max over elements after my chunk
        const float sf3 = fmaxf(e3, tail);
        const float sf2 = fmaxf(e2, sf3);
        const float sf1 = fmaxf(e1, sf2);
        const float sf0 = fmaxf(e0, sf1);
        const float u0 = s0 * sf0, u1 = s1 * sf1, u2 = s2 * sf2, u3 = s3 * sf3;
        us[4 * t] = u0; us[4 * t + 1] = u1; us[4 * t + 2] = u2; us[4 * t + 3] = u3;
        __syncthreads();

        // ---- warp 0: L = exact 5th-largest achievable score u ----
        if (t < 32) {
            float l5[TK];
#pragma unroll
            for (int k = 0; k < TK; k++) l5[k] = NEGINF;
            for (int p = t; p < SB; p += 32) {
                float v = us[p];
                if (v > l5[TK - 1]) {
                    float ts = v;
#pragma unroll
                    for (int k = 0; k < TK; k++) {
                        if (ts > l5[k]) { float a = l5[k]; l5[k] = ts; ts = a; }
                    }
                }
            }
            float Lv = NEGINF;
#pragma unroll
            for (int r = 0; r < TK; r++) {
                float m = l5[0];
#pragma unroll
                for (int o = 16; o; o >>= 1) m = fmaxf(m, __shfl_xor_sync(FULLM, m, o));
                unsigned bal = __ballot_sync(FULLM, l5[0] == m);
                if (lane == (__ffs(bal) - 1)) {
#pragma unroll
                    for (int k = 0; k < TK - 1; k++) l5[k] = l5[k + 1];
                    l5[TK - 1] = NEGINF;
                }
                Lv = m;
            }
            if (lane == 0) sh_L = Lv;
        }
        __syncthreads();
        const float L = sh_L;   // L <= true 5th-largest pair score

        // ---- collect surviving rows (u_i >= L) ----
        {
            const float uu[4] = { u0, u1, u2, u3 };
            const float ss[4] = { s0, s1, s2, s3 };
#pragma unroll
            for (int k = 0; k < 4; k++) {
                if (uu[k] >= L) {
                    int p = atomicAdd(&rown, 1);
                    rlist[p] = 4 * t + k; rs[p] = ss[k];
                }
            }
        }
        __syncthreads();
        const int R = rown;

        // ---- cooperative scan: all threads stride over each surviving row ----
        for (int r = 0; r < R; r++) {
            const int i = rlist[r];
            const float spi = rs[r];
            const int base = i << 10;
            for (int j = i + t; j < SB; j += NTHR) {
                float v = spi * ep[j];
                if (v >= L) {
                    int p = atomicAdd(&cnt, 1);
                    if (p < CAP) { cands[p] = v; candi[p] = base + j; }
                }
            }
        }
        __syncthreads();
        const int C = cnt;

        if (C <= CAP) {
            // ---- warp 0: top-5 over candidates ----
            if (t < 32) {
                float s5[TK]; int i5[TK];
#pragma unroll
                for (int k = 0; k < TK; k++) { s5[k] = -1.0f; i5[k] = 0x7fffffff; }
                for (int p = t; p < C; p += 32) tryins(s5, i5, cands[p], candi[p]);
#pragma unroll
                for (int r = 0; r < TK; r++) {
                    float v = s5[0]; int id = i5[0];
#pragma unroll
                    for (int o = 16; o; o >>= 1) {
                        float ov = __shfl_xor_sync(FULLM, v, o);
                        int   oi = __shfl_xor_sync(FULLM, id, o);
                        if (better(ov, oi, v, id)) { v = ov; id = oi; }
                    }
                    if (s5[0] == v && i5[0] == id) {
#pragma unroll
                        for (int k = 0; k < TK - 1; k++) { s5[k] = s5[k + 1]; i5[k] = i5[k + 1]; }
                        s5[TK - 1] = -1.0f; i5[TK - 1] = 0x7fffffff;
                    }
                    if (lane == 0) { fin_s[r] = v; fin_i[r] = id; }
                }
            }
        } else if (t == 0) {
            // pathological overflow: exact serial scan (never triggers on benign data)
            float s5[TK]; int i5[TK];
#pragma unroll
            for (int k = 0; k < TK; k++) { s5[k] = -1.0f; i5[k] = 0x7fffffff; }
            for (int i = 0; i < SB; i++) {
                float spi = sp[i];
                for (int j = i; j < SB; j++) tryins(s5, i5, spi * ep[j], (i << 10) + j);
            }
#pragma unroll
            for (int k = 0; k < TK; k++) { fin_s[k] = s5[k]; fin_i[k] = i5[k]; }
        }
        __syncthreads();

        // ---- GIoU on lanes 0..4, warp reduce ----
        if (t < 32) {
            float val = 0.0f;
            if (t < TK) {
                float conf = fin_s[t]; int fid = fin_i[t];
                int i = fid >> 10, j = fid & (SB - 1);
                float smsf = (float)smsp[b];
                float pst = (float)i + smsf;
                float ped = (float)j + smsf;
                float best = -INFINITY;
#pragma unroll
                for (int g = 0; g < NG; g++) {
                    float gst = gt[(b * NG + g) * 2 + 0];
                    float ged = gt[(b * NG + g) * 2 + 1];
                    float inter = fmaxf(fminf(ped, ged) - fmaxf(pst, gst), 0.0f);
                    float uni   = (ped - pst) + (ged - gst) - inter;
                    float iou   = inter / fmaxf(uni, EPSF);
                    float enc   = fmaxf(fmaxf(ped, ged) - fminf(pst, gst), 0.0f);
                    float gi    = iou - (enc - uni) / fmaxf(enc, EPSF);
                    best = fmaxf(best, gi);
                }
                float d = conf - best;
                val = d * d;
            }
#pragma unroll
            for (int off = 16; off; off >>= 1)
                val += __shfl_down_sync(FULLM, val, off);
            if (t == 0) g_spans[b] = val;
        }
    } else {
        // ================= label loss (weighted BCE x3) =================
        const int lb = blk - NB;
        const float4* fp4 = (const float4*)fp;
        float acc = 0.0f;
        for (int idx = lb * NTHR + t; idx < NB * SB; idx += NLBLK * NTHR) {
            float4 v = fp4[idx];
            acc += wbce(v.x, sl[idx]);
            acc += wbce(v.y, ml[idx]);
            acc += wbce(v.z, el[idx]);
        }
#pragma unroll
        for (int off = 16; off; off >>= 1)
            acc += __shfl_down_sync(FULLM, acc, off);
        if (lane == 0) wsum[w] = acc;
        __syncthreads();
        if (t == 0) {
            float s = 0.0f;
#pragma unroll
            for (int ww = 0; ww < NTHR / 32; ww++) s += wsum[ww];
            g_labels[lb] = s;
        }
    }

    // ================= last block finalizes =================
    if (t == 0) {
        __threadfence();
        unsigned v = atomicAdd(&g_done, 1u);
        if (v == (unsigned)(NB + NLBLK - 1)) {
            __threadfence();
            float s = 0.0f, l = 0.0f;
#pragma unroll
            for (int i = 0; i < NB; i++)    s += g_spans[i];
#pragma unroll
            for (int i = 0; i < NLBLK; i++) l += g_labels[i];
            out[0] = s * (1.0f / 160.0f) + l * (1.0f / 32768.0f);
            g_done = 0;
        }
    }
}

extern "C" void kernel_launch(void* const* d_in, const int* in_sizes, int n_in,
                              void* d_out, int out_size) {
    const float* fp  = (const float*)d_in[0];
    const float* sl  = (const float*)d_in[1];
    const float* ml  = (const float*)d_in[2];
    const float* el  = (const float*)d_in[3];
    const float* gt  = (const float*)d_in[4];
    const int*   sms = (const int*)d_in[5];

    crit_all<<<NB + NLBLK, NTHR>>>(fp, sl, ml, el, gt, sms, (float*)d_out);
}

// round 4
// speedup vs baseline: 11.9107x; 1.0603x over previous
#include <cuda_runtime.h>
#include <math.h>
#include <float.h>

#define SB     1024
#define NB     32
#define NG     5
#define TK     5
#define EPSF   1e-7f
#define NLBLK  128                  // 128*256 = 32768 = NB*SB -> 1 elem/thread
#define NTHR   256
#define NWARP  (NTHR / 32)
#define TOTB   (NB + NLBLK)
#define CAP    1024
#define NEGINF (-1e30f)
#define FULLM  0xffffffffu

__device__ float g_spans[NB];
__device__ float g_labels[NLBLK];
__device__ unsigned g_done = 0;

__device__ __forceinline__ float sigf(float x) { return 1.0f / (1.0f + __expf(-x)); }

// jax.lax.top_k ordering: larger value first; ties -> smaller flat index first
__device__ __forceinline__ bool better(float s1, int i1, float s2, int i2) {
    return (s1 > s2) || (s1 == s2 && i1 < i2);
}

__device__ __forceinline__ void tryins(float* s5, int* i5, float v, int id) {
    if (v > s5[TK - 1] || (v == s5[TK - 1] && id < i5[TK - 1])) {
        float ts = v; int ti = id;
#pragma unroll
        for (int k = 0; k < TK; k++) {
            if (better(ts, ti, s5[k], i5[k])) {
                float a = s5[k]; int b = i5[k];
                s5[k] = ts; i5[k] = ti;
                ts = a; ti = b;
            }
        }
    }
}

__device__ __forceinline__ float wbce(float x, float tg) {
    float p = fminf(fmaxf(sigf(x), EPSF), 1.0f - EPSF);
    float b = -(tg * __logf(p) + (1.0f - tg) * __logf(1.0f - p));
    float d = fabsf(p - tg);
    return b * d * d;
}

__global__ void __launch_bounds__(NTHR)
crit_all(const float* __restrict__ fp, const float* __restrict__ sl,
         const float* __restrict__ ml, const float* __restrict__ el,
         const float* __restrict__ gt, const int* __restrict__ smsp,
         float* __restrict__ out) {
    __shared__ __align__(16) float sp[SB];
    __shared__ __align__(16) float ep[SB];
    __shared__ __align__(16) float cands[CAP];
    __shared__ int   candi[CAP];
    __shared__ int   rlist[SB];
    __shared__ float rs[SB];
    __shared__ float warpM[NWARP];
    __shared__ float wtop[NWARP * TK];
    __shared__ float gtl[NG * 2];
    __shared__ int   smsl;
    __shared__ float fb_s[TK];
    __shared__ int   fb_i[TK];
    __shared__ int   cnt, rown;
    __shared__ float wsum[NWARP];
    __shared__ int   islast;

    const int t    = threadIdx.x;
    const int blk  = blockIdx.x;
    const int lane = t & 31;
    const int w    = t >> 5;

    if (blk < NB) {
        // ================= spans loss: one block per batch =================
        const int b = blk;
        // prefetch GIoU operands first so their latency overlaps everything
        if (t < NG * 2) gtl[t] = gt[b * NG * 2 + t];
        if (t == NG * 2) smsl = smsp[b];
        if (t == 0) { cnt = 0; rown = 0; }

        const float4* fp4 = ((const float4*)fp) + b * SB;
        float4 va = fp4[4 * t], vb = fp4[4 * t + 1], vc = fp4[4 * t + 2], vd = fp4[4 * t + 3];
        const float s0 = sigf(va.x), s1 = sigf(vb.x), s2 = sigf(vc.x), s3 = sigf(vd.x);
        const float e0 = sigf(va.z), e1 = sigf(vb.z), e2 = sigf(vc.z), e3 = sigf(vd.z);
        sp[4 * t] = s0; sp[4 * t + 1] = s1; sp[4 * t + 2] = s2; sp[4 * t + 3] = s3;
        ep[4 * t] = e0; ep[4 * t + 1] = e1; ep[4 * t + 2] = e2; ep[4 * t + 3] = e3;

        // ---- suffix max of ep via shfl ----
        float inc = fmaxf(fmaxf(e0, e1), fmaxf(e2, e3));
#pragma unroll
        for (int o = 1; o < 32; o <<= 1) {
            float v = __shfl_down_sync(FULLM, inc, o);
            if (lane + o < 32) inc = fmaxf(inc, v);
        }
        float excl = __shfl_down_sync(FULLM, inc, 1);
        if (lane == 31) excl = NEGINF;
        if (lane == 0) warpM[w] = inc;
        __syncthreads();                                    // (1)
        float suffW = NEGINF;
#pragma unroll
        for (int ww = 0; ww < NWARP; ww++)
            if (ww > w) suffW = fmaxf(suffW, warpM[ww]);
        const float tail = fmaxf(excl, suffW);
        const float sf3 = fmaxf(e3, tail);
        const float sf2 = fmaxf(e2, sf3);
        const float sf1 = fmaxf(e1, sf2);
        const float sf0 = fmaxf(e0, sf1);
        const float u0 = s0 * sf0, u1 = s1 * sf1, u2 = s2 * sf2, u3 = s3 * sf3;

        // ---- per-warp exact top-5 of u (values only, register-resident) ----
        {
            float a0 = u0, a1 = u1, a2 = u2, a3 = u3, wval = NEGINF;
#pragma unroll
            for (int r = 0; r < TK; r++) {
                float lm = fmaxf(fmaxf(a0, a1), fmaxf(a2, a3));
                float m = lm;
#pragma unroll
                for (int o = 16; o; o >>= 1) m = fmaxf(m, __shfl_xor_sync(FULLM, m, o));
                unsigned bal = __ballot_sync(FULLM, lm == m);
                if (lane == (__ffs(bal) - 1)) {
                    if (a0 == m) a0 = NEGINF;
                    else if (a1 == m) a1 = NEGINF;
                    else if (a2 == m) a2 = NEGINF;
                    else a3 = NEGINF;
                }
                if (lane == r) wval = m;
            }
            if (lane < TK) wtop[w * TK + lane] = wval;
        }
        __syncthreads();                                    // (2)

        // ---- every warp redundantly merges the 40 warp-top values -> L ----
        float L;
        {
            float a = (lane < NWARP * TK) ? wtop[lane] : NEGINF;
            float c = (32 + lane < NWARP * TK) ? wtop[32 + lane] : NEGINF;
            float m = NEGINF;
#pragma unroll
            for (int r = 0; r < TK; r++) {
                float lm = fmaxf(a, c);
                m = lm;
#pragma unroll
                for (int o = 16; o; o >>= 1) m = fmaxf(m, __shfl_xor_sync(FULLM, m, o));
                unsigned bal = __ballot_sync(FULLM, lm == m);
                if (lane == (__ffs(bal) - 1)) {
                    if (a == m) a = NEGINF; else c = NEGINF;
                }
            }
            L = m;   // exact global 5th-largest achievable score
        }

        // ---- collect surviving rows (u_i >= L) ----
        {
            const float uu[4] = { u0, u1, u2, u3 };
            const float ss[4] = { s0, s1, s2, s3 };
#pragma unroll
            for (int k = 0; k < 4; k++) {
                if (uu[k] >= L) {
                    int p = atomicAdd(&rown, 1);
                    rlist[p] = 4 * t + k; rs[p] = ss[k];
                }
            }
        }
        __syncthreads();                                    // (3)
        const int R = rown;

        // ---- cooperative scan of surviving rows ----
        for (int r = 0; r < R; r++) {
            const int i = rlist[r];
            const float spi = rs[r];
            const int base = i << 10;
            for (int j = i + t; j < SB; j += NTHR) {
                float v = spi * ep[j];
                if (v >= L) {
                    int p = atomicAdd(&cnt, 1);
                    if (p < CAP) { cands[p] = v; candi[p] = base + j; }
                }
            }
        }
        __syncthreads();                                    // (4)
        const int C = cnt;

        if (C > CAP) {       // pathological fallback: exact serial scan
            if (t == 0) {
                float s5[TK]; int i5[TK];
#pragma unroll
                for (int k = 0; k < TK; k++) { s5[k] = -1.0f; i5[k] = 0x7fffffff; }
                for (int i = 0; i < SB; i++) {
                    float spi = sp[i];
                    for (int j = i; j < SB; j++) tryins(s5, i5, spi * ep[j], (i << 10) + j);
                }
#pragma unroll
                for (int k = 0; k < TK; k++) { fb_s[k] = s5[k]; fb_i[k] = i5[k]; }
            }
            __syncthreads();
        }

        // ---- warp 0: final top-5 + GIoU entirely in registers ----
        if (t < 32) {
            float fs[TK]; int fi[TK];
            if (C <= CAP) {
                float s5[TK]; int i5[TK];
#pragma unroll
                for (int k = 0; k < TK; k++) { s5[k] = -1.0f; i5[k] = 0x7fffffff; }
                for (int p = lane; p < C; p += 32) tryins(s5, i5, cands[p], candi[p]);
#pragma unroll
                for (int r = 0; r < TK; r++) {
                    float v = s5[0]; int id = i5[0];
#pragma unroll
                    for (int o = 16; o; o >>= 1) {
                        float ov = __shfl_xor_sync(FULLM, v, o);
                        int   oi = __shfl_xor_sync(FULLM, id, o);
                        if (better(ov, oi, v, id)) { v = ov; id = oi; }
                    }
                    if (s5[0] == v && i5[0] == id) {   // (v,id) unique -> one lane shifts
#pragma unroll
                        for (int k = 0; k < TK - 1; k++) { s5[k] = s5[k + 1]; i5[k] = i5[k + 1]; }
                        s5[TK - 1] = -1.0f; i5[TK - 1] = 0x7fffffff;
                    }
                    fs[r] = v; fi[r] = id;             // all lanes hold winners
                }
            } else {
#pragma unroll
                for (int k = 0; k < TK; k++) { fs[k] = fb_s[k]; fi[k] = fb_i[k]; }
            }

            float val = 0.0f;
            if (lane < TK) {
                float conf = fs[lane]; int fid = fi[lane];
                int i = fid >> 10, j = fid & (SB - 1);
                float smsf = (float)smsl;
                float pst = (float)i + smsf;
                float ped = (float)j + smsf;
                float best = -INFINITY;
#pragma unroll
                for (int g = 0; g < NG; g++) {
                    float gst = gtl[2 * g + 0];
                    float ged = gtl[2 * g + 1];
                    float inter = fmaxf(fminf(ped, ged) - fmaxf(pst, gst), 0.0f);
                    float uni   = (ped - pst) + (ged - gst) - inter;
                    float iou   = inter / fmaxf(uni, EPSF);
                    float enc   = fmaxf(fmaxf(ped, ged) - fminf(pst, gst), 0.0f);
                    float gi    = iou - (enc - uni) / fmaxf(enc, EPSF);
                    best = fmaxf(best, gi);
                }
                float d = conf - best;
                val = d * d;
            }
#pragma unroll
            for (int off = 16; off; off >>= 1)
                val += __shfl_down_sync(FULLM, val, off);
            if (lane == 0) g_spans[b] = val;
        }
    } else {
        // ================= label loss: exactly one element per thread =================
        const int lb = blk - NB;
        const int gid = lb * NTHR + t;           // < 32768 always
        float4 v = ((const float4*)fp)[gid];
        float acc = wbce(v.x, sl[gid]) + wbce(v.y, ml[gid]) + wbce(v.z, el[gid]);
#pragma unroll
        for (int off = 16; off; off >>= 1)
            acc += __shfl_down_sync(FULLM, acc, off);
        if (lane == 0) wsum[w] = acc;
        __syncthreads();
        if (t == 0) {
            float s = 0.0f;
#pragma unroll
            for (int ww = 0; ww < NWARP; ww++) s += wsum[ww];
            g_labels[lb] = s;
        }
    }

    // ================= last block finalizes (block-wide reduce) =================
    __threadfence();
    if (t == 0) {
        unsigned v = atomicAdd(&g_done, 1u);
        islast = (v == (unsigned)(TOTB - 1)) ? 1 : 0;
    }
    __syncthreads();
    if (islast) {
        __threadfence();
        float v = 0.0f;
        if (t < NB)    v  = g_spans[t]  * (1.0f / 160.0f);
        if (t < NLBLK) v += g_labels[t] * (1.0f / 32768.0f);
#pragma unroll
        for (int off = 16; off; off >>= 1)
            v += __shfl_down_sync(FULLM, v, off);
        if (lane == 0) wsum[w] = v;
        __syncthreads();
        if (t == 0) {
            float s = 0.0f;
#pragma unroll
            for (int ww = 0; ww < NWARP; ww++) s += wsum[ww];
            out[0] = s;
            g_done = 0;
        }
    }
}

extern "C" void kernel_launch(void* const* d_in, const int* in_sizes, int n_in,
                              void* d_out, int out_size) {
    const float* fp  = (const float*)d_in[0];
    const float* sl  = (const float*)d_in[1];
    const float* ml  = (const float*)d_in[2];
    const float* el  = (const float*)d_in[3];
    const float* gt  = (const float*)d_in[4];
    const int*   sms = (const int*)d_in[5];

    crit_all<<<TOTB, NTHR>>>(fp, sl, ml, el, gt, sms, (float*)d_out);
}

// round 5
// speedup vs baseline: 15.5569x; 1.3061x over previous
#include <cuda_runtime.h>
#include <math.h>
#include <float.h>

#define SB     1024
#define NB     32
#define NG     5
#define TK     5
#define EPSF   1e-7f
#define NLBLK  128
#define NTHR   256
#define NWARP  (NTHR / 32)
#define TOTB   (NB + NLBLK)
#define CAP    1024
#define NEGINF (-1e30f)
#define FULLM  0xffffffffu
#define IMAXU  0x7fffffffu

__device__ float g_spans[NB];
__device__ float g_labels[NLBLK];
__device__ unsigned g_done = 0;

__device__ __forceinline__ float sigf(float x) {
    return __fdividef(1.0f, 1.0f + __expf(-x));
}

__device__ __forceinline__ bool better(float s1, int i1, float s2, int i2) {
    return (s1 > s2) || (s1 == s2 && i1 < i2);
}

__device__ __forceinline__ void tryins(float* s5, int* i5, float v, int id) {
    if (v > s5[TK - 1] || (v == s5[TK - 1] && id < i5[TK - 1])) {
        float ts = v; int ti = id;
#pragma unroll
        for (int k = 0; k < TK; k++) {
            if (better(ts, ti, s5[k], i5[k])) {
                float a = s5[k]; int b = i5[k];
                s5[k] = ts; i5[k] = ti;
                ts = a; ti = b;
            }
        }
    }
}

__device__ __forceinline__ float wbce(float x, float tg) {
    float p = fminf(fmaxf(sigf(x), EPSF), 1.0f - EPSF);
    float b = -(tg * __logf(p) + (1.0f - tg) * __logf(1.0f - p));
    float d = fabsf(p - tg);
    return b * d * d;
}

__global__ void __launch_bounds__(NTHR)
crit_all(const float* __restrict__ fp, const float* __restrict__ sl,
         const float* __restrict__ ml, const float* __restrict__ el,
         const float* __restrict__ gt, const int* __restrict__ smsp,
         float* __restrict__ out) {
    __shared__ __align__(16) float sp[SB];
    __shared__ __align__(16) float ep[SB];
    __shared__ __align__(16) float cands[CAP];
    __shared__ int   candi[CAP];
    __shared__ int   rlist[SB];
    __shared__ float rs[SB];
    __shared__ float warpM[NWARP];
    __shared__ float wtop[NWARP * TK];
    __shared__ float gtl[NG * 2];
    __shared__ int   smsl;
    __shared__ float fb_s[TK];
    __shared__ int   fb_i[TK];
    __shared__ int   cnt, rown;
    __shared__ float wsum[NWARP];
    __shared__ int   islast;

    const int t    = threadIdx.x;
    const int blk  = blockIdx.x;
    const int lane = t & 31;
    const int w    = t >> 5;

    if (blk < NB) {
        // ================= spans loss: one block per batch =================
        const int b = blk;
        if (t < NG * 2) gtl[t] = gt[b * NG * 2 + t];
        if (t == NG * 2) smsl = smsp[b];
        if (t == 0) { cnt = 0; rown = 0; }

        const float4* fp4 = ((const float4*)fp) + b * SB;
        float4 va = fp4[4 * t], vb = fp4[4 * t + 1], vc = fp4[4 * t + 2], vd = fp4[4 * t + 3];
        const float s0 = sigf(va.x), s1 = sigf(vb.x), s2 = sigf(vc.x), s3 = sigf(vd.x);
        const float e0 = sigf(va.z), e1 = sigf(vb.z), e2 = sigf(vc.z), e3 = sigf(vd.z);
        sp[4 * t] = s0; sp[4 * t + 1] = s1; sp[4 * t + 2] = s2; sp[4 * t + 3] = s3;
        ep[4 * t] = e0; ep[4 * t + 1] = e1; ep[4 * t + 2] = e2; ep[4 * t + 3] = e3;

        // ---- suffix max of ep: 5-step warp scan (dependency inherent) ----
        float inc = fmaxf(fmaxf(e0, e1), fmaxf(e2, e3));
#pragma unroll
        for (int o = 1; o < 32; o <<= 1) {
            float v = __shfl_down_sync(FULLM, inc, o);
            if (lane + o < 32) inc = fmaxf(inc, v);
        }
        float excl = __shfl_down_sync(FULLM, inc, 1);
        if (lane == 31) excl = NEGINF;
        if (lane == 0) warpM[w] = inc;
        __syncthreads();                                    // (1)
        float suffW = NEGINF;
#pragma unroll
        for (int ww = 0; ww < NWARP; ww++)
            if (ww > w) suffW = fmaxf(suffW, warpM[ww]);
        const float tail = fmaxf(excl, suffW);
        const float sf3 = fmaxf(e3, tail);
        const float sf2 = fmaxf(e2, sf3);
        const float sf1 = fmaxf(e1, sf2);
        const float sf0 = fmaxf(e0, sf1);
        const float u0 = s0 * sf0, u1 = s1 * sf1, u2 = s2 * sf2, u3 = s3 * sf3;

        // ---- per-warp exact top-5 of u via redux (values > 0) ----
        {
            float a0 = u0, a1 = u1, a2 = u2, a3 = u3;
            float wval = 0.0f;
#pragma unroll
            for (int r = 0; r < TK; r++) {
                float lm = fmaxf(fmaxf(a0, a1), fmaxf(a2, a3));
                unsigned m = __reduce_max_sync(FULLM, __float_as_uint(lm));
                unsigned bal = __ballot_sync(FULLM, __float_as_uint(lm) == m);
                if (lane == (__ffs(bal) - 1)) {          // one lane pops one instance
                    if (__float_as_uint(a0) == m) a0 = 0.0f;
                    else if (__float_as_uint(a1) == m) a1 = 0.0f;
                    else if (__float_as_uint(a2) == m) a2 = 0.0f;
                    else a3 = 0.0f;
                }
                if (lane == r) wval = __uint_as_float(m);
            }
            if (lane < TK) wtop[w * TK + lane] = wval;
        }
        __syncthreads();                                    // (2)

        // ---- every warp merges the 40 warp-top values -> exact global 5th = L ----
        float L;
        {
            float a = wtop[lane < NWARP * TK ? lane : 0];
            if (lane >= NWARP * TK) a = 0.0f;
            float c = (32 + lane < NWARP * TK) ? wtop[32 + lane] : 0.0f;
            unsigned m = 0;
#pragma unroll
            for (int r = 0; r < TK; r++) {
                float lm = fmaxf(a, c);
                m = __reduce_max_sync(FULLM, __float_as_uint(lm));
                unsigned bal = __ballot_sync(FULLM, __float_as_uint(lm) == m);
                if (lane == (__ffs(bal) - 1)) {
                    if (__float_as_uint(a) == m) a = 0.0f; else c = 0.0f;
                }
            }
            L = __uint_as_float(m);
        }

        // ---- collect surviving rows (u_i >= L) ----
        {
            const float uu[4] = { u0, u1, u2, u3 };
            const float ss[4] = { s0, s1, s2, s3 };
#pragma unroll
            for (int k = 0; k < 4; k++) {
                if (uu[k] >= L) {
                    int p = atomicAdd(&rown, 1);
                    rlist[p] = 4 * t + k; rs[p] = ss[k];
                }
            }
        }
        __syncthreads();                                    // (3)
        const int R = rown;

        // ---- cooperative scan of surviving rows ----
        for (int r = 0; r < R; r++) {
            const int i = rlist[r];
            const float spi = rs[r];
            const int base = i << 10;
            for (int j = i + t; j < SB; j += NTHR) {
                float v = spi * ep[j];
                if (v >= L) {
                    int p = atomicAdd(&cnt, 1);
                    if (p < CAP) { cands[p] = v; candi[p] = base + j; }
                }
            }
        }
        __syncthreads();                                    // (4)
        const int C = cnt;

        if (C > CAP) {       // pathological fallback: exact serial scan
            if (t == 0) {
                float s5[TK]; int i5[TK];
#pragma unroll
                for (int k = 0; k < TK; k++) { s5[k] = -1.0f; i5[k] = IMAXU; }
                for (int i = 0; i < SB; i++) {
                    float spi = sp[i];
                    for (int j = i; j < SB; j++) tryins(s5, i5, spi * ep[j], (i << 10) + j);
                }
#pragma unroll
                for (int k = 0; k < TK; k++) { fb_s[k] = s5[k]; fb_i[k] = i5[k]; }
            }
            __syncthreads();
        }

        // ---- warp 0: final top-5 via redux pairs + GIoU in registers ----
        if (t < 32) {
            float fs[TK]; int fi[TK];
            if (C <= CAP) {
                float s5[TK]; int i5[TK];
#pragma unroll
                for (int k = 0; k < TK; k++) { s5[k] = 0.0f; i5[k] = IMAXU; }
                for (int p = lane; p < C; p += 32) tryins(s5, i5, cands[p], candi[p]);
#pragma unroll
                for (int r = 0; r < TK; r++) {
                    unsigned vb_ = __float_as_uint(s5[0]);
                    unsigned m = __reduce_max_sync(FULLM, vb_);
                    unsigned idc = (vb_ == m) ? (unsigned)i5[0] : IMAXU;
                    unsigned widx = __reduce_min_sync(FULLM, idc);
                    if (vb_ == m && (unsigned)i5[0] == widx) {   // winner lane pops
#pragma unroll
                        for (int k = 0; k < TK - 1; k++) { s5[k] = s5[k + 1]; i5[k] = i5[k + 1]; }
                        s5[TK - 1] = 0.0f; i5[TK - 1] = IMAXU;
                    }
                    fs[r] = __uint_as_float(m); fi[r] = (int)widx;
                }
            } else {
#pragma unroll
                for (int k = 0; k < TK; k++) { fs[k] = fb_s[k]; fi[k] = fb_i[k]; }
            }

            float val = 0.0f;
            if (lane < TK) {
                float conf = fs[lane]; int fid = fi[lane];
                int i = fid >> 10, j = fid & (SB - 1);
                float smsf = (float)smsl;
                float pst = (float)i + smsf;
                float ped = (float)j + smsf;
                float best = -INFINITY;
#pragma unroll
                for (int g = 0; g < NG; g++) {
                    float gst = gtl[2 * g + 0];
                    float ged = gtl[2 * g + 1];
                    float inter = fmaxf(fminf(ped, ged) - fmaxf(pst, gst), 0.0f);
                    float uni   = (ped - pst) + (ged - gst) - inter;
                    float iou   = __fdividef(inter, fmaxf(uni, EPSF));
                    float enc   = fmaxf(fmaxf(ped, ged) - fminf(pst, gst), 0.0f);
                    float gi    = iou - __fdividef(enc - uni, fmaxf(enc, EPSF));
                    best = fmaxf(best, gi);
                }
                float d = conf - best;
                val = d * d;
            }
#pragma unroll
            for (int off = 16; off; off >>= 1)
                val += __shfl_down_sync(FULLM, val, off);
            if (lane == 0) g_spans[b] = val;
        }
    } else {
        // ================= label loss: one element per thread =================
        const int lb = blk - NB;
        const int gid = lb * NTHR + t;
        float4 v = ((const float4*)fp)[gid];
        float acc = wbce(v.x, sl[gid]) + wbce(v.y, ml[gid]) + wbce(v.z, el[gid]);
#pragma unroll
        for (int off = 16; off; off >>= 1)
            acc += __shfl_down_sync(FULLM, acc, off);
        if (lane == 0) wsum[w] = acc;
        __syncthreads();
        if (t == 0) {
            float s = 0.0f;
#pragma unroll
            for (int ww = 0; ww < NWARP; ww++) s += wsum[ww];
            g_labels[lb] = s;
        }
    }

    // ================= last block finalizes (block-wide reduce) =================
    __threadfence();
    if (t == 0) {
        unsigned v = atomicAdd(&g_done, 1u);
        islast = (v == (unsigned)(TOTB - 1)) ? 1 : 0;
    }
    __syncthreads();
    if (islast) {
        __threadfence();
        float v = 0.0f;
        if (t < NB)    v  = g_spans[t]  * (1.0f / 160.0f);
        if (t < NLBLK) v += g_labels[t] * (1.0f / 32768.0f);
#pragma unroll
        for (int off = 16; off; off >>= 1)
            v += __shfl_down_sync(FULLM, v, off);
        if (lane == 0) wsum[w] = v;
        __syncthreads();
        if (t == 0) {
            float s = 0.0f;
#pragma unroll
            for (int ww = 0; ww < NWARP; ww++) s += wsum[ww];
            out[0] = s;
            g_done = 0;
        }
    }
}

extern "C" void kernel_launch(void* const* d_in, const int* in_sizes, int n_in,
                              void* d_out, int out_size) {
    const float* fp  = (const float*)d_in[0];
    const float* sl  = (const float*)d_in[1];
    const float* ml  = (const float*)d_in[2];
    const float* el  = (const float*)d_in[3];
    const float* gt  = (const float*)d_in[4];
    const int*   sms = (const int*)d_in[5];

    crit_all<<<TOTB, NTHR>>>(fp, sl, ml, el, gt, sms, (float*)d_out);
}